// round 10
// baseline (speedup 1.0000x reference)
#include <cuda_runtime.h>
#include <cuda_bf16.h>
#include <cstdint>

#define BB_   2
#define LL_   2048
#define EE_   1024
#define HH_   16
#define DH_   64
#define FF_   4096
#define NTOK  (BB_*LL_)
#define NZ    (BB_*HH_)

// ---------------- scratch ----------------
__device__ float g_xn[NTOK*EE_];
__device__ __nv_bfloat16 g_xnh[NTOK*EE_];
__device__ __nv_bfloat16 g_xnl[NTOK*EE_];
__device__ __nv_bfloat16 g_qh[NTOK*EE_];
__device__ __nv_bfloat16 g_ql[NTOK*EE_];
__device__ __nv_bfloat16 g_kh[NTOK*EE_];
__device__ __nv_bfloat16 g_kl[NTOK*EE_];
__device__ __nv_bfloat16 g_wqhT[EE_*EE_], g_wqlT[EE_*EE_];
__device__ __nv_bfloat16 g_wkhT[EE_*EE_], g_wklT[EE_*EE_];
__device__ float g_v [NTOK*EE_];
__device__ float g_ctx[NTOK*EE_];
__device__ float g_hidden[NTOK*EE_];
__device__ float g_hn[NTOK*EE_];
__device__ float g_up[(size_t)NTOK*FF_];
__device__ float g_S[(size_t)NZ*LL_*LL_];

// ---------------- helpers ----------------
__device__ __forceinline__ uint32_t f2tf(float x){
    uint32_t r; asm("cvt.rna.tf32.f32 %0, %1;" : "=r"(r) : "f"(x)); return r;
}
__device__ __forceinline__ void mma_tf32(float c[4], const uint32_t a[4], const uint32_t b[2]){
    asm volatile("mma.sync.aligned.m16n8k8.row.col.f32.tf32.tf32.f32 "
        "{%0,%1,%2,%3},{%4,%5,%6,%7},{%8,%9},{%0,%1,%2,%3};"
        : "+f"(c[0]), "+f"(c[1]), "+f"(c[2]), "+f"(c[3])
        : "r"(a[0]), "r"(a[1]), "r"(a[2]), "r"(a[3]), "r"(b[0]), "r"(b[1]));
}
__device__ __forceinline__ void mma_bf16(float c[4], const uint32_t a[4], const uint32_t b[2]){
    asm volatile("mma.sync.aligned.m16n8k16.row.col.f32.bf16.bf16.f32 "
        "{%0,%1,%2,%3},{%4,%5,%6,%7},{%8,%9},{%0,%1,%2,%3};"
        : "+f"(c[0]), "+f"(c[1]), "+f"(c[2]), "+f"(c[3])
        : "r"(a[0]), "r"(a[1]), "r"(a[2]), "r"(a[3]), "r"(b[0]), "r"(b[1]));
}
__device__ __forceinline__ void cp16(void* dst, const void* src){
    uint32_t d = (uint32_t)__cvta_generic_to_shared(dst);
    asm volatile("cp.async.cg.shared.global [%0], [%1], 16;" :: "r"(d), "l"(src));
}
__device__ __forceinline__ void cp_commit(){ asm volatile("cp.async.commit_group;" ::: "memory"); }
template<int N> __device__ __forceinline__ void cp_wait(){
    asm volatile("cp.async.wait_group %0;" :: "n"(N) : "memory");
}
__device__ __forceinline__ ushort bfb(float x){
    return __bfloat16_as_ushort(__float2bfloat16_rn(x));
}
__device__ __forceinline__ float bff(ushort u){
    return __bfloat162float(__ushort_as_bfloat16(u));
}

// ---------------- weight split+transpose: W[k][n] fp32 -> T[n][k] bf16 hi/lo ----------------
__global__ void wsplitT_k(const float* __restrict__ W,
                          __nv_bfloat16* __restrict__ Th, __nv_bfloat16* __restrict__ Tl)
{
    __shared__ float t[32][33];
    const int bn = blockIdx.x*32, bk = blockIdx.y*32;
    const int c = threadIdx.x & 31, r = threadIdx.x >> 5;   // r 0..7
    #pragma unroll
    for (int i=0;i<4;i++)
        t[r+i*8][c] = W[(size_t)(bk + r + i*8)*EE_ + bn + c];
    __syncthreads();
    #pragma unroll
    for (int i=0;i<4;i++){
        const int n = bn + r + i*8, k = bk + c;
        float v = t[c][r+i*8];
        ushort h = bfb(v);
        Th[(size_t)n*EE_ + k] = __ushort_as_bfloat16(h);
        Tl[(size_t)n*EE_ + k] = __float2bfloat16_rn(v - bff(h));
    }
}

// ---------------- LayerNorm (optionally emits bf16 hi/lo) ----------------
template<bool BF>
__global__ void ln_k(const float* __restrict__ X, const float* __restrict__ w,
                     const float* __restrict__ bb, float* __restrict__ O,
                     __nv_bfloat16* __restrict__ OH, __nv_bfloat16* __restrict__ OL)
{
    __shared__ float red[256];
    const int t = threadIdx.x;
    const size_t off = (size_t)blockIdx.x * EE_;
    float4 v = *(const float4*)(X + off + t*4);
    red[t] = v.x + v.y + v.z + v.w;
    __syncthreads();
    #pragma unroll
    for (int s = 128; s > 0; s >>= 1){ if (t < s) red[t] += red[t+s]; __syncthreads(); }
    float mu = red[0] * (1.f/1024.f);
    __syncthreads();
    float d0 = v.x-mu, d1 = v.y-mu, d2 = v.z-mu, d3 = v.w-mu;
    red[t] = d0*d0 + d1*d1 + d2*d2 + d3*d3;
    __syncthreads();
    #pragma unroll
    for (int s = 128; s > 0; s >>= 1){ if (t < s) red[t] += red[t+s]; __syncthreads(); }
    float inv = rsqrtf(red[0] * (1.f/1024.f) + 1e-5f);
    float4 wv = *(const float4*)(w + t*4);
    float4 bv = *(const float4*)(bb + t*4);
    float o0 = d0*inv*wv.x + bv.x, o1 = d1*inv*wv.y + bv.y;
    float o2 = d2*inv*wv.z + bv.z, o3 = d3*inv*wv.w + bv.w;
    float4 o; o.x=o0; o.y=o1; o.z=o2; o.w=o3;
    *(float4*)(O + off + t*4) = o;
    if (BF){
        ushort h0=bfb(o0), h1=bfb(o1), h2=bfb(o2), h3=bfb(o3);
        ushort4 hv = {h0,h1,h2,h3};
        ushort4 lv = {bfb(o0-bff(h0)), bfb(o1-bff(h1)), bfb(o2-bff(h2)), bfb(o3-bff(h3))};
        *(ushort4*)(OH + off + t*4) = hv;
        *(ushort4*)(OL + off + t*4) = lv;
    }
}

// ---------------- bf16-split GEMM (Q/K proj): C = A @ B^T + bias -> bf16 hi/lo ----------------
// A [m][k] bf16 hi/lo, B [n][k] bf16 hi/lo (pre-transposed weights).
// smem stage: Ah 0, Al 10240, Bh 20480, Bl 30720 (row stride 80B = 40 bf16), stage 40960B.
#define BFSTG 40960

__global__ void __launch_bounds__(256, 1) gemm_bf_k(
    const __nv_bfloat16* __restrict__ Ah, const __nv_bfloat16* __restrict__ Al,
    const __nv_bfloat16* __restrict__ Bh, const __nv_bfloat16* __restrict__ Bl,
    const float* __restrict__ bias,
    __nv_bfloat16* __restrict__ Ch, __nv_bfloat16* __restrict__ Cl,
    int M, int N, int K)
{
    extern __shared__ char smc[];
    const int tid  = threadIdx.x;
    const int bm   = blockIdx.y*128, bn = blockIdx.x*128;
    const int lane = tid & 31, warp = tid >> 5;
    const int wm   = warp >> 2, wn = warp & 3;      // 2x4, warp tile 64x32
    const int gid  = lane >> 2, t4 = lane & 3;

    float acc[4][4][4];
    #pragma unroll
    for (int a=0;a<4;a++)
    #pragma unroll
    for (int b=0;b<4;b++)
    #pragma unroll
    for (int c=0;c<4;c++) acc[a][b][c] = 0.f;

    const int crow = tid >> 1, c2 = tid & 1;    // copy roles: 2 thr/row, 32B each
    const __nv_bfloat16* Ap_h = Ah + (size_t)(bm+crow)*K + c2*16;
    const __nv_bfloat16* Ap_l = Al + (size_t)(bm+crow)*K + c2*16;
    const __nv_bfloat16* Bp_h = Bh + (size_t)(bn+crow)*K + c2*16;
    const __nv_bfloat16* Bp_l = Bl + (size_t)(bn+crow)*K + c2*16;
    const int KT = K >> 5;

    auto issue = [&](int t){
        char* base = smc + (t&1)*BFSTG;
        const int ko = t*32;
        const int doff = crow*80 + c2*32;
        cp16(base + doff,              Ap_h + ko);
        cp16(base + doff + 16,         Ap_h + ko + 8);
        cp16(base + 10240 + doff,      Ap_l + ko);
        cp16(base + 10240 + doff + 16, Ap_l + ko + 8);
        cp16(base + 20480 + doff,      Bp_h + ko);
        cp16(base + 20480 + doff + 16, Bp_h + ko + 8);
        cp16(base + 30720 + doff,      Bp_l + ko);
        cp16(base + 30720 + doff + 16, Bp_l + ko + 8);
        cp_commit();
    };

    issue(0);
    for (int t = 0; t < KT; t++){
        if (t+1 < KT){ issue(t+1); cp_wait<1>(); }
        else         { cp_wait<0>(); }
        __syncthreads();
        const uint32_t* base = (const uint32_t*)(smc + (t&1)*BFSTG);
        const uint32_t* sAh = base;          // word stride 20 per row
        const uint32_t* sAl = base + 2560;
        const uint32_t* sBh = base + 5120;
        const uint32_t* sBl = base + 7680;
        #pragma unroll
        for (int ks=0;ks<2;ks++){
            const int ko = ks*8 + t4;
            uint32_t ah[4][4], al[4][4], bh[4][2], bl[4][2];
            #pragma unroll
            for (int mi=0;mi<4;mi++){
                const int r = (wm*64 + mi*16 + gid)*20 + ko;
                ah[mi][0]=sAh[r]; ah[mi][1]=sAh[r+160]; ah[mi][2]=sAh[r+4]; ah[mi][3]=sAh[r+164];
                al[mi][0]=sAl[r]; al[mi][1]=sAl[r+160]; al[mi][2]=sAl[r+4]; al[mi][3]=sAl[r+164];
            }
            #pragma unroll
            for (int ni=0;ni<4;ni++){
                const int c = (wn*32 + ni*8 + gid)*20 + ko;
                bh[ni][0]=sBh[c]; bh[ni][1]=sBh[c+4];
                bl[ni][0]=sBl[c]; bl[ni][1]=sBl[c+4];
            }
            #pragma unroll
            for (int mi=0;mi<4;mi++)
            #pragma unroll
            for (int ni=0;ni<4;ni++){
                mma_bf16(acc[mi][ni], ah[mi], bh[ni]);
                mma_bf16(acc[mi][ni], ah[mi], bl[ni]);
                mma_bf16(acc[mi][ni], al[mi], bh[ni]);
            }
        }
        __syncthreads();
    }

    #pragma unroll
    for (int mi=0;mi<4;mi++)
    #pragma unroll
    for (int ni=0;ni<4;ni++){
        const int row0 = bm + wm*64 + mi*16 + gid;
        const int col0 = bn + wn*32 + ni*8 + t4*2;
        #pragma unroll
        for (int half=0; half<2; half++){
            const int row = row0 + half*8;
            float v0 = acc[mi][ni][half*2+0] + bias[col0];
            float v1 = acc[mi][ni][half*2+1] + bias[col0+1];
            ushort h0 = bfb(v0), h1 = bfb(v1);
            ushort2 hv = {h0, h1};
            ushort2 lv = {bfb(v0-bff(h0)), bfb(v1-bff(h1))};
            *(ushort2*)(Ch + (size_t)row*N + col0) = hv;
            *(ushort2*)(Cl + (size_t)row*N + col0) = lv;
        }
    }
}

// ---------------- tf32 GEMM (V/O/FFN): C = epi(A @ W + bias (+res)) ----------------
#define GSS 8832

template<int EPI, int MINB>   // EPI: 0 bias, 1 bias+res, 2 bias+gelu
__global__ void __launch_bounds__(256, MINB) gemm_k(
    const float* __restrict__ A, const float* __restrict__ W,
    const float* __restrict__ bias, const float* __restrict__ res,
    float* __restrict__ C, int M, int N, int K)
{
    extern __shared__ float sm[];
    const int tid  = threadIdx.x;
    const int bm   = blockIdx.y*128, bn = blockIdx.x*128;
    const int lane = tid & 31, warp = tid >> 5;
    const int wm   = warp >> 2, wn = warp & 3;
    const int gid  = lane >> 2, t4 = lane & 3;

    float acc[4][4][4];
    #pragma unroll
    for (int a=0;a<4;a++)
    #pragma unroll
    for (int b=0;b<4;b++)
    #pragma unroll
    for (int c=0;c<4;c++) acc[a][b][c] = 0.f;

    const int ar = tid >> 3, ac4 = tid & 7;
    const int br = tid >> 5, bc4 = tid & 31;
    const float* Ap = A + (size_t)(bm+ar)*K + ac4*4;
    const float* Wp = W + (size_t)br*N + bn + bc4*4;
    const int KT = K >> 5;

    auto issue = [&](int t){
        float* As = sm + (t&1)*GSS;
        float* Bs = As + 4608;
        const float* ap = Ap + t*32;
        const float* wp = Wp + (size_t)t*32*N;
        #pragma unroll
        for (int i=0;i<4;i++) cp16(As + (ar+32*i)*36 + ac4*4, ap + (size_t)(32*i)*K);
        #pragma unroll
        for (int i=0;i<4;i++) cp16(Bs + (br+8*i)*132 + bc4*4, wp + (size_t)(8*i)*N);
        cp_commit();
    };

    issue(0);
    for (int t = 0; t < KT; t++){
        if (t+1 < KT){ issue(t+1); cp_wait<1>(); }
        else         { cp_wait<0>(); }
        __syncthreads();
        const float* As = sm + (t&1)*GSS;
        const float* Bs = As + 4608;
        #pragma unroll
        for (int ks=0;ks<4;ks++){
            uint32_t ah[4][4], bh[4][2];
            #pragma unroll
            for (int mi=0;mi<4;mi++){
                const int r0 = (wm*64 + mi*16 + gid)*36 + ks*8 + t4;
                ah[mi][0]=f2tf(As[r0]); ah[mi][1]=f2tf(As[r0+8*36]);
                ah[mi][2]=f2tf(As[r0+4]); ah[mi][3]=f2tf(As[r0+8*36+4]);
            }
            #pragma unroll
            for (int ni=0;ni<4;ni++){
                const int c0 = wn*32 + ni*8 + gid;
                bh[ni][0]=f2tf(Bs[(ks*8+t4)*132 + c0]);
                bh[ni][1]=f2tf(Bs[(ks*8+t4+4)*132 + c0]);
            }
            #pragma unroll
            for (int mi=0;mi<4;mi++)
            #pragma unroll
            for (int ni=0;ni<4;ni++)
                mma_tf32(acc[mi][ni], ah[mi], bh[ni]);
        }
        __syncthreads();
    }

    #pragma unroll
    for (int mi=0;mi<4;mi++)
    #pragma unroll
    for (int ni=0;ni<4;ni++){
        const int row0 = bm + wm*64 + mi*16 + gid;
        const int col0 = bn + wn*32 + ni*8 + t4*2;
        #pragma unroll
        for (int i=0;i<4;i++){
            const int row = row0 + ((i>=2)?8:0);
            const int col = col0 + (i&1);
            float v = acc[mi][ni][i] + bias[col];
            if (EPI == 1) v += res[(size_t)row*N + col];
            if (EPI == 2) v = 0.5f*v*(1.0f + erff(v*0.70710678118654752f));
            C[(size_t)row*N + col] = v;
        }
    }
}

// ---------------- attention scores (bf16-split): S[z,l,m] = 8 * q.k ----------------
// smem: sQh 0, sQl 18432, sKh 36864, sKl 55296 (each 128 rows x 144B, stride 36 words)
__global__ void __launch_bounds__(256) attn_score_bf(
    const __nv_bfloat16* __restrict__ Qh, const __nv_bfloat16* __restrict__ Ql,
    const __nv_bfloat16* __restrict__ Kh, const __nv_bfloat16* __restrict__ Kl,
    float* __restrict__ S)
{
    extern __shared__ char smc[];
    const int tid  = threadIdx.x;
    const int z = blockIdx.z, b = z >> 4, h = z & 15;
    const int bm = blockIdx.y*128, bn = blockIdx.x*128;
    const int lane = tid & 31, warp = tid >> 5;
    const int wm = warp >> 2, wn = warp & 3;
    const int gid = lane >> 2, t4 = lane & 3;

    // load: 2 thr/row, 4 chunks of 16B each per tensor
    {
        const int crow = tid >> 1, c2 = tid & 1;
        const size_t qoff = ((size_t)(b*LL_ + bm + crow)*EE_ + h*64) + c2*32;
        const size_t koff = ((size_t)(b*LL_ + bn + crow)*EE_ + h*64) + c2*32;
        const int doff = crow*144 + c2*64;
        #pragma unroll
        for (int j=0;j<4;j++){
            cp16(smc + doff + j*16,         Qh + qoff + j*8);
            cp16(smc + 18432 + doff + j*16, Ql + qoff + j*8);
            cp16(smc + 36864 + doff + j*16, Kh + koff + j*8);
            cp16(smc + 55296 + doff + j*16, Kl + koff + j*8);
        }
        cp_commit();
    }
    cp_wait<0>();
    __syncthreads();

    float acc[4][4][4];
    #pragma unroll
    for (int a=0;a<4;a++)
    #pragma unroll
    for (int c=0;c<4;c++)
    #pragma unroll
    for (int i=0;i<4;i++) acc[a][c][i] = 0.f;

    const uint32_t* sQh = (const uint32_t*)smc;
    const uint32_t* sQl = sQh + 4608;
    const uint32_t* sKh = sQh + 9216;
    const uint32_t* sKl = sQh + 13824;

    #pragma unroll
    for (int ks=0;ks<4;ks++){
        const int ko = ks*8 + t4;
        uint32_t ah[4][4], al[4][4], bh[4][2], bl[4][2];
        #pragma unroll
        for (int mi=0;mi<4;mi++){
            const int r = (wm*64 + mi*16 + gid)*36 + ko;
            ah[mi][0]=sQh[r]; ah[mi][1]=sQh[r+288]; ah[mi][2]=sQh[r+4]; ah[mi][3]=sQh[r+292];
            al[mi][0]=sQl[r]; al[mi][1]=sQl[r+288]; al[mi][2]=sQl[r+4]; al[mi][3]=sQl[r+292];
        }
        #pragma unroll
        for (int ni=0;ni<4;ni++){
            const int c = (wn*32 + ni*8 + gid)*36 + ko;
            bh[ni][0]=sKh[c]; bh[ni][1]=sKh[c+4];
            bl[ni][0]=sKl[c]; bl[ni][1]=sKl[c+4];
        }
        #pragma unroll
        for (int mi=0;mi<4;mi++)
        #pragma unroll
        for (int ni=0;ni<4;ni++){
            mma_bf16(acc[mi][ni], ah[mi], bh[ni]);
            mma_bf16(acc[mi][ni], ah[mi], bl[ni]);
            mma_bf16(acc[mi][ni], al[mi], bh[ni]);
        }
    }

    float* Sz = S + (size_t)z*LL_*LL_;
    #pragma unroll
    for (int mi=0;mi<4;mi++)
    #pragma unroll
    for (int ni=0;ni<4;ni++){
        const int row0 = bm + wm*64 + mi*16 + gid;
        const int col0 = bn + wn*32 + ni*8 + t4*2;
        #pragma unroll
        for (int i=0;i<4;i++){
            const int row = row0 + ((i>=2)?8:0);
            const int col = col0 + (i&1);
            Sz[(size_t)row*LL_ + col] = 8.0f * acc[mi][ni][i];
        }
    }
}

// ---------------- row softmax ----------------
__global__ void softmax_k(float* __restrict__ S)
{
    __shared__ float red[256];
    const int t = threadIdx.x;
    float4* row = (float4*)(S + (size_t)blockIdx.y*LL_*LL_ + (size_t)blockIdx.x*LL_);
    float4 v0 = row[t], v1 = row[t+256];
    float m = fmaxf(fmaxf(fmaxf(v0.x,v0.y), fmaxf(v0.z,v0.w)),
                    fmaxf(fmaxf(v1.x,v1.y), fmaxf(v1.z,v1.w)));
    red[t] = m; __syncthreads();
    #pragma unroll
    for (int s=128;s>0;s>>=1){ if (t<s) red[t] = fmaxf(red[t], red[t+s]); __syncthreads(); }
    m = red[0]; __syncthreads();
    v0.x = expf(v0.x-m); v0.y = expf(v0.y-m); v0.z = expf(v0.z-m); v0.w = expf(v0.w-m);
    v1.x = expf(v1.x-m); v1.y = expf(v1.y-m); v1.z = expf(v1.z-m); v1.w = expf(v1.w-m);
    red[t] = v0.x+v0.y+v0.z+v0.w + v1.x+v1.y+v1.z+v1.w;
    __syncthreads();
    #pragma unroll
    for (int s=128;s>0;s>>=1){ if (t<s) red[t] += red[t+s]; __syncthreads(); }
    const float inv = 1.0f / red[0];
    v0.x*=inv; v0.y*=inv; v0.z*=inv; v0.w*=inv;
    v1.x*=inv; v1.y*=inv; v1.z*=inv; v1.w*=inv;
    row[t] = v0; row[t+256] = v1;
}

// ---------------- ctx = P @ V (tf32) ----------------
#define VSS 6912

__global__ void __launch_bounds__(256, 2) attn_av_k(
    const float* __restrict__ P, const float* __restrict__ V, float* __restrict__ Ctx)
{
    extern __shared__ float sm[];
    const int tid  = threadIdx.x;
    const int z = blockIdx.y, b = z >> 4, h = z & 15;
    const int bm = blockIdx.x*128;
    const int lane = tid & 31, warp = tid >> 5;
    const int wm = warp >> 1, wn = warp & 1;
    const int gid = lane >> 2, t4 = lane & 3;

    float acc[2][4][4];
    #pragma unroll
    for (int a=0;a<2;a++)
    #pragma unroll
    for (int c=0;c<4;c++)
    #pragma unroll
    for (int i=0;i<4;i++) acc[a][c][i] = 0.f;

    const int ar = tid >> 3, ac4 = tid & 7;
    const int vr = tid >> 4, vc4 = tid & 15;
    const float* Pp = P + (size_t)z*LL_*LL_ + (size_t)(bm+ar)*LL_ + ac4*4;
    const float* Vp = V + ((size_t)(b*LL_ + vr)*HH_ + h)*DH_ + vc4*4;
    const int KT = LL_/32;

    auto issue = [&](int t){
        float* Ps = sm + (t&1)*VSS;
        float* Vs = Ps + 4608;
        const int k0 = t*32;
        #pragma unroll
        for (int i=0;i<4;i++) cp16(Ps + (ar+32*i)*36 + ac4*4, Pp + k0 + (size_t)(32*i)*LL_);
        #pragma unroll
        for (int i=0;i<2;i++) cp16(Vs + (vr+16*i)*72 + vc4*4, Vp + (size_t)(k0+16*i)*1024);
        cp_commit();
    };

    issue(0);
    for (int t = 0; t < KT; t++){
        if (t+1 < KT){ issue(t+1); cp_wait<1>(); }
        else         { cp_wait<0>(); }
        __syncthreads();
        const float* Ps = sm + (t&1)*VSS;
        const float* Vs = Ps + 4608;
        #pragma unroll
        for (int ks=0;ks<4;ks++){
            uint32_t a[2][4], bfr[4][2];
            #pragma unroll
            for (int mi=0;mi<2;mi++){
                const int r0 = (wm*32 + mi*16 + gid)*36 + ks*8 + t4;
                a[mi][0]=f2tf(Ps[r0]);     a[mi][1]=f2tf(Ps[r0+8*36]);
                a[mi][2]=f2tf(Ps[r0+4]);   a[mi][3]=f2tf(Ps[r0+8*36+4]);
            }
            #pragma unroll
            for (int ni=0;ni<4;ni++){
                const int c0 = wn*32 + ni*8 + gid;
                bfr[ni][0] = f2tf(Vs[(ks*8+t4)*72 + c0]);
                bfr[ni][1] = f2tf(Vs[(ks*8+t4+4)*72 + c0]);
            }
            #pragma unroll
            for (int mi=0;mi<2;mi++)
            #pragma unroll
            for (int ni=0;ni<4;ni++)
                mma_tf32(acc[mi][ni], a[mi], bfr[ni]);
        }
        __syncthreads();
    }

    #pragma unroll
    for (int mi=0;mi<2;mi++)
    #pragma unroll
    for (int ni=0;ni<4;ni++){
        const int row0 = bm + wm*32 + mi*16 + gid;
        const int col0 = wn*32 + ni*8 + t4*2;
        #pragma unroll
        for (int i=0;i<4;i++){
            const int row = row0 + ((i>=2)?8:0);
            const int col = col0 + (i&1);
            Ctx[((size_t)(b*LL_ + row)*HH_ + h)*DH_ + col] = acc[mi][ni][i];
        }
    }
}

// ---------------- launch ----------------
extern "C" void kernel_launch(void* const* d_in, const int* in_sizes, int n_in,
                              void* d_out, int out_size)
{
    const float* x     = (const float*)d_in[0];
    const float* ln1_w = (const float*)d_in[1];
    const float* ln1_b = (const float*)d_in[2];
    const float* wq    = (const float*)d_in[3];
    const float* bq    = (const float*)d_in[4];
    const float* wk    = (const float*)d_in[5];
    const float* bk    = (const float*)d_in[6];
    const float* wv    = (const float*)d_in[7];
    const float* bv    = (const float*)d_in[8];
    const float* wo    = (const float*)d_in[9];
    const float* bo    = (const float*)d_in[10];
    const float* ln2_w = (const float*)d_in[11];
    const float* ln2_b = (const float*)d_in[12];
    const float* wu    = (const float*)d_in[13];
    const float* bu    = (const float*)d_in[14];
    const float* wd    = (const float*)d_in[15];
    const float* bd    = (const float*)d_in[16];
    float* out = (float*)d_out;

    float *xn,*v,*ctx,*hidden,*hn,*up,*S;
    __nv_bfloat16 *xnh,*xnl,*qh,*ql,*kh,*kl,*wqhT,*wqlT,*wkhT,*wklT;
    cudaGetSymbolAddress((void**)&xn,   g_xn);
    cudaGetSymbolAddress((void**)&xnh,  g_xnh);
    cudaGetSymbolAddress((void**)&xnl,  g_xnl);
    cudaGetSymbolAddress((void**)&qh,   g_qh);
    cudaGetSymbolAddress((void**)&ql,   g_ql);
    cudaGetSymbolAddress((void**)&kh,   g_kh);
    cudaGetSymbolAddress((void**)&kl,   g_kl);
    cudaGetSymbolAddress((void**)&wqhT, g_wqhT);
    cudaGetSymbolAddress((void**)&wqlT, g_wqlT);
    cudaGetSymbolAddress((void**)&wkhT, g_wkhT);
    cudaGetSymbolAddress((void**)&wklT, g_wklT);
    cudaGetSymbolAddress((void**)&v,    g_v);
    cudaGetSymbolAddress((void**)&ctx,  g_ctx);
    cudaGetSymbolAddress((void**)&hidden, g_hidden);
    cudaGetSymbolAddress((void**)&hn,   g_hn);
    cudaGetSymbolAddress((void**)&up,   g_up);
    cudaGetSymbolAddress((void**)&S,    g_S);

    const int SMG  = 2*GSS*4;     // 70656
    const int SMV  = 2*VSS*4;     // 55296
    const int SMBF = 2*BFSTG;     // 81920
    const int SMSC = 4*18432;     // 73728
    cudaFuncSetAttribute(gemm_bf_k,    cudaFuncAttributeMaxDynamicSharedMemorySize, SMBF);
    cudaFuncSetAttribute(attn_score_bf,cudaFuncAttributeMaxDynamicSharedMemorySize, SMSC);
    cudaFuncSetAttribute(gemm_k<0,2>,  cudaFuncAttributeMaxDynamicSharedMemorySize, SMG);
    cudaFuncSetAttribute(gemm_k<1,2>,  cudaFuncAttributeMaxDynamicSharedMemorySize, SMG);
    cudaFuncSetAttribute(gemm_k<2,2>,  cudaFuncAttributeMaxDynamicSharedMemorySize, SMG);
    cudaFuncSetAttribute(attn_av_k,    cudaFuncAttributeMaxDynamicSharedMemorySize, SMV);

    const dim3 blk(256);
    const dim3 gE(EE_/128, NTOK/128);
    const dim3 gF(FF_/128, NTOK/128);
    const dim3 gT(EE_/32, EE_/32);

    // 0. weight split+transpose for Q/K
    wsplitT_k<<<gT, blk>>>(wq, wqhT, wqlT);
    wsplitT_k<<<gT, blk>>>(wk, wkhT, wklT);
    // 1. LN1 (fp32 + bf16 hi/lo)
    ln_k<true><<<NTOK, blk>>>(x, ln1_w, ln1_b, xn, xnh, xnl);
    // 2. Q, K (bf16-split), V (tf32)
    gemm_bf_k<<<gE, blk, SMBF>>>(xnh, xnl, wqhT, wqlT, bq, qh, ql, NTOK, EE_, EE_);
    gemm_bf_k<<<gE, blk, SMBF>>>(xnh, xnl, wkhT, wklT, bk, kh, kl, NTOK, EE_, EE_);
    gemm_k<0,2><<<gE, blk, SMG>>>(xn, wv, bv, nullptr, v, NTOK, EE_, EE_);
    // 3. scores (bf16-split), softmax, context (tf32)
    attn_score_bf<<<dim3(LL_/128, LL_/128, NZ), blk, SMSC>>>(qh, ql, kh, kl, S);
    softmax_k    <<<dim3(LL_, NZ), blk>>>(S);
    attn_av_k    <<<dim3(LL_/128, NZ), blk, SMV>>>(S, v, ctx);
    // 4. O proj + residual
    gemm_k<1,2><<<gE, blk, SMG>>>(ctx, wo, bo, x, hidden, NTOK, EE_, EE_);
    // 5. LN2 + FFN
    ln_k<false><<<NTOK, blk>>>(hidden, ln2_w, ln2_b, hn, nullptr, nullptr);
    gemm_k<2,2><<<gF, blk, SMG>>>(hn, wu, bu, nullptr, up, NTOK, FF_, EE_);
    gemm_k<1,2><<<gE, blk, SMG>>>(up, wd, bd, hidden, out, NTOK, EE_, FF_);
    (void)in_sizes; (void)n_in; (void)out_size;
}

// round 12
// speedup vs baseline: 1.4805x; 1.4805x over previous
#include <cuda_runtime.h>
#include <cstdint>

#define BB_   2
#define LL_   2048
#define EE_   1024
#define HH_   16
#define DH_   64
#define FF_   4096
#define NTOK  (BB_*LL_)
#define NZ    (BB_*HH_)

// ---------------- scratch ----------------
__device__ float g_xn[NTOK*EE_];
__device__ float g_q [NTOK*EE_];
__device__ float g_k [NTOK*EE_];
__device__ float g_v [NTOK*EE_];
__device__ float g_ctx[NTOK*EE_];
__device__ float g_hidden[NTOK*EE_];
__device__ float g_hn[NTOK*EE_];
__device__ float g_up[(size_t)NTOK*FF_];
__device__ float g_S[(size_t)NZ*LL_*LL_];

// ---------------- helpers ----------------
__device__ __forceinline__ uint32_t f2tf(float x){
    uint32_t r; asm("cvt.rna.tf32.f32 %0, %1;" : "=r"(r) : "f"(x)); return r;
}
__device__ __forceinline__ void mma_tf32(float c[4], const uint32_t a[4], const uint32_t b[2]){
    asm volatile("mma.sync.aligned.m16n8k8.row.col.f32.tf32.tf32.f32 "
        "{%0,%1,%2,%3},{%4,%5,%6,%7},{%8,%9},{%0,%1,%2,%3};"
        : "+f"(c[0]), "+f"(c[1]), "+f"(c[2]), "+f"(c[3])
        : "r"(a[0]), "r"(a[1]), "r"(a[2]), "r"(a[3]), "r"(b[0]), "r"(b[1]));
}
__device__ __forceinline__ void cp16(void* dst, const void* src){
    uint32_t d = (uint32_t)__cvta_generic_to_shared(dst);
    asm volatile("cp.async.cg.shared.global [%0], [%1], 16;" :: "r"(d), "l"(src));
}
__device__ __forceinline__ void cp_commit(){ asm volatile("cp.async.commit_group;" ::: "memory"); }
template<int N> __device__ __forceinline__ void cp_wait(){
    asm volatile("cp.async.wait_group %0;" :: "n"(N) : "memory");
}

// ---------------- LayerNorm ----------------
__global__ void ln_k(const float* __restrict__ X, const float* __restrict__ w,
                     const float* __restrict__ bb, float* __restrict__ O)
{
    __shared__ float red[256];
    const int t = threadIdx.x;
    const size_t off = (size_t)blockIdx.x * EE_;
    float4 v = *(const float4*)(X + off + t*4);
    red[t] = v.x + v.y + v.z + v.w;
    __syncthreads();
    #pragma unroll
    for (int s = 128; s > 0; s >>= 1){ if (t < s) red[t] += red[t+s]; __syncthreads(); }
    float mu = red[0] * (1.f/1024.f);
    __syncthreads();
    float d0 = v.x-mu, d1 = v.y-mu, d2 = v.z-mu, d3 = v.w-mu;
    red[t] = d0*d0 + d1*d1 + d2*d2 + d3*d3;
    __syncthreads();
    #pragma unroll
    for (int s = 128; s > 0; s >>= 1){ if (t < s) red[t] += red[t+s]; __syncthreads(); }
    float inv = rsqrtf(red[0] * (1.f/1024.f) + 1e-5f);
    float4 wv = *(const float4*)(w + t*4);
    float4 bv = *(const float4*)(bb + t*4);
    float4 o;
    o.x = d0*inv*wv.x + bv.x;  o.y = d1*inv*wv.y + bv.y;
    o.z = d2*inv*wv.z + bv.z;  o.w = d3*inv*wv.w + bv.w;
    *(float4*)(O + off + t*4) = o;
}

// ---------------- tf32 GEMM: C[M,N] = epi(A[M,K] @ W[K,N] + bias (+res)) ----------------
// EPI: 0 bias, 1 bias+res, 2 bias+gelu
// SPLIT: 0 = single tf32, 1 = A-operand split (2 MMAs: hh + lh)
#define GSS 8832   // 128*36 + 32*132

template<int EPI, int SPLIT, int MINB>
__global__ void __launch_bounds__(256, MINB) gemm_k(
    const float* __restrict__ A, const float* __restrict__ W,
    const float* __restrict__ bias, const float* __restrict__ res,
    float* __restrict__ C, int M, int N, int K)
{
    extern __shared__ float sm[];
    const int tid  = threadIdx.x;
    const int bm   = blockIdx.y*128, bn = blockIdx.x*128;
    const int lane = tid & 31, warp = tid >> 5;
    const int wm   = warp >> 2, wn = warp & 3;      // 2x4 warp grid, warp tile 64x32
    const int gid  = lane >> 2, t4 = lane & 3;

    float acc[4][4][4];
    #pragma unroll
    for (int a=0;a<4;a++)
    #pragma unroll
    for (int b=0;b<4;b++)
    #pragma unroll
    for (int c=0;c<4;c++) acc[a][b][c] = 0.f;

    const int ar = tid >> 3, ac4 = tid & 7;
    const int br = tid >> 5, bc4 = tid & 31;
    const float* Ap = A + (size_t)(bm+ar)*K + ac4*4;
    const float* Wp = W + (size_t)br*N + bn + bc4*4;
    const int KT = K >> 5;

    auto issue = [&](int t){
        float* As = sm + (t&1)*GSS;
        float* Bs = As + 4608;
        const float* ap = Ap + t*32;
        const float* wp = Wp + (size_t)t*32*N;
        #pragma unroll
        for (int i=0;i<4;i++) cp16(As + (ar+32*i)*36 + ac4*4, ap + (size_t)(32*i)*K);
        #pragma unroll
        for (int i=0;i<4;i++) cp16(Bs + (br+8*i)*132 + bc4*4, wp + (size_t)(8*i)*N);
        cp_commit();
    };

    issue(0);
    for (int t = 0; t < KT; t++){
        if (t+1 < KT){ issue(t+1); cp_wait<1>(); }
        else         { cp_wait<0>(); }
        __syncthreads();
        const float* As = sm + (t&1)*GSS;
        const float* Bs = As + 4608;
        #pragma unroll
        for (int ks=0;ks<4;ks++){
            uint32_t ah[4][4], al[4][4], bh[4][2];
            #pragma unroll
            for (int mi=0;mi<4;mi++){
                const int r0 = (wm*64 + mi*16 + gid)*36 + ks*8 + t4;
                float x0 = As[r0], x1 = As[r0+8*36], x2 = As[r0+4], x3 = As[r0+8*36+4];
                ah[mi][0]=f2tf(x0); ah[mi][1]=f2tf(x1); ah[mi][2]=f2tf(x2); ah[mi][3]=f2tf(x3);
                if (SPLIT){
                    al[mi][0]=f2tf(x0-__uint_as_float(ah[mi][0]));
                    al[mi][1]=f2tf(x1-__uint_as_float(ah[mi][1]));
                    al[mi][2]=f2tf(x2-__uint_as_float(ah[mi][2]));
                    al[mi][3]=f2tf(x3-__uint_as_float(ah[mi][3]));
                }
            }
            #pragma unroll
            for (int ni=0;ni<4;ni++){
                const int c0 = wn*32 + ni*8 + gid;
                bh[ni][0]=f2tf(Bs[(ks*8+t4)*132 + c0]);
                bh[ni][1]=f2tf(Bs[(ks*8+t4+4)*132 + c0]);
            }
            #pragma unroll
            for (int mi=0;mi<4;mi++)
            #pragma unroll
            for (int ni=0;ni<4;ni++){
                mma_tf32(acc[mi][ni], ah[mi], bh[ni]);
                if (SPLIT) mma_tf32(acc[mi][ni], al[mi], bh[ni]);
            }
        }
        __syncthreads();
    }

    #pragma unroll
    for (int mi=0;mi<4;mi++)
    #pragma unroll
    for (int ni=0;ni<4;ni++){
        const int row0 = bm + wm*64 + mi*16 + gid;
        const int col0 = bn + wn*32 + ni*8 + t4*2;
        #pragma unroll
        for (int i=0;i<4;i++){
            const int row = row0 + ((i>=2)?8:0);
            const int col = col0 + (i&1);
            float v = acc[mi][ni][i] + bias[col];
            if (EPI == 1) v += res[(size_t)row*N + col];
            if (EPI == 2) v = 0.5f*v*(1.0f + erff(v*0.70710678118654752f));
            C[(size_t)row*N + col] = v;
        }
    }
}

// ---------------- attention scores: S[z,l,m] = 8 * q.k  (full 3-MMA split) ----------------
__global__ void __launch_bounds__(256) attn_score_k(
    const float* __restrict__ Q, const float* __restrict__ Kx, float* __restrict__ S)
{
    __shared__ float Qs[128*36];
    __shared__ float Ks[128*36];
    const int tid  = threadIdx.x;
    const int z = blockIdx.z, b = z >> 4, h = z & 15;
    const int bm = blockIdx.y*128, bn = blockIdx.x*128;
    const int lane = tid & 31, warp = tid >> 5;
    const int wm = warp >> 2, wn = warp & 3;
    const int gid = lane >> 2, t4 = lane & 3;

    float acc[4][4][4];
    #pragma unroll
    for (int a=0;a<4;a++)
    #pragma unroll
    for (int c=0;c<4;c++)
    #pragma unroll
    for (int i=0;i<4;i++) acc[a][c][i] = 0.f;

    const int ar = tid >> 3, ac4 = tid & 7;
    const float* Qp = Q  + ((size_t)(b*LL_ + bm + ar)*HH_ + h)*DH_ + ac4*4;
    const float* Kp = Kx + ((size_t)(b*LL_ + bn + ar)*HH_ + h)*DH_ + ac4*4;

    #pragma unroll
    for (int kt = 0; kt < 2; kt++){
        float4 qr[4], kr[4];
        #pragma unroll
        for (int i=0;i<4;i++){
            qr[i] = *(const float4*)(Qp + kt*32 + (size_t)(32*i)*1024);
            kr[i] = *(const float4*)(Kp + kt*32 + (size_t)(32*i)*1024);
        }
        if (kt) __syncthreads();
        #pragma unroll
        for (int i=0;i<4;i++){
            *(float4*)(Qs + (ar+32*i)*36 + ac4*4) = qr[i];
            *(float4*)(Ks + (ar+32*i)*36 + ac4*4) = kr[i];
        }
        __syncthreads();
        #pragma unroll
        for (int ks=0;ks<4;ks++){
            uint32_t ah[4][4], al[4][4], bh[4][2], bl[4][2];
            #pragma unroll
            for (int mi=0;mi<4;mi++){
                const int r0 = (wm*64 + mi*16 + gid)*36 + ks*8 + t4;
                float x0 = Qs[r0], x1 = Qs[r0+8*36], x2 = Qs[r0+4], x3 = Qs[r0+8*36+4];
                ah[mi][0]=f2tf(x0); ah[mi][1]=f2tf(x1); ah[mi][2]=f2tf(x2); ah[mi][3]=f2tf(x3);
                al[mi][0]=f2tf(x0-__uint_as_float(ah[mi][0]));
                al[mi][1]=f2tf(x1-__uint_as_float(ah[mi][1]));
                al[mi][2]=f2tf(x2-__uint_as_float(ah[mi][2]));
                al[mi][3]=f2tf(x3-__uint_as_float(ah[mi][3]));
            }
            #pragma unroll
            for (int ni=0;ni<4;ni++){
                const int c0 = wn*32 + ni*8 + gid;
                float y0 = Ks[c0*36 + ks*8 + t4];
                float y1 = Ks[c0*36 + ks*8 + t4 + 4];
                bh[ni][0]=f2tf(y0); bh[ni][1]=f2tf(y1);
                bl[ni][0]=f2tf(y0-__uint_as_float(bh[ni][0]));
                bl[ni][1]=f2tf(y1-__uint_as_float(bh[ni][1]));
            }
            #pragma unroll
            for (int mi=0;mi<4;mi++)
            #pragma unroll
            for (int ni=0;ni<4;ni++){
                mma_tf32(acc[mi][ni], ah[mi], bh[ni]);
                mma_tf32(acc[mi][ni], ah[mi], bl[ni]);
                mma_tf32(acc[mi][ni], al[mi], bh[ni]);
            }
        }
    }

    float* Sz = S + (size_t)z*LL_*LL_;
    #pragma unroll
    for (int mi=0;mi<4;mi++)
    #pragma unroll
    for (int ni=0;ni<4;ni++){
        const int row0 = bm + wm*64 + mi*16 + gid;
        const int col0 = bn + wn*32 + ni*8 + t4*2;
        #pragma unroll
        for (int i=0;i<4;i++){
            const int row = row0 + ((i>=2)?8:0);
            const int col = col0 + (i&1);
            Sz[(size_t)row*LL_ + col] = 8.0f * acc[mi][ni][i];
        }
    }
}

// ---------------- row softmax (warp-shuffle reductions) ----------------
__global__ void softmax_k(float* __restrict__ S)
{
    __shared__ float redm[8];
    __shared__ float reds[8];
    const int t = threadIdx.x, lane = t & 31, w = t >> 5;
    float4* row = (float4*)(S + (size_t)blockIdx.y*LL_*LL_ + (size_t)blockIdx.x*LL_);
    float4 v0 = row[t], v1 = row[t+256];
    float m = fmaxf(fmaxf(fmaxf(v0.x,v0.y), fmaxf(v0.z,v0.w)),
                    fmaxf(fmaxf(v1.x,v1.y), fmaxf(v1.z,v1.w)));
    #pragma unroll
    for (int o=16;o>0;o>>=1) m = fmaxf(m, __shfl_xor_sync(0xFFFFFFFFu, m, o));
    if (lane == 0) redm[w] = m;
    __syncthreads();
    m = redm[0];
    #pragma unroll
    for (int i=1;i<8;i++) m = fmaxf(m, redm[i]);
    v0.x = expf(v0.x-m); v0.y = expf(v0.y-m); v0.z = expf(v0.z-m); v0.w = expf(v0.w-m);
    v1.x = expf(v1.x-m); v1.y = expf(v1.y-m); v1.z = expf(v1.z-m); v1.w = expf(v1.w-m);
    float s = v0.x+v0.y+v0.z+v0.w + v1.x+v1.y+v1.z+v1.w;
    #pragma unroll
    for (int o=16;o>0;o>>=1) s += __shfl_xor_sync(0xFFFFFFFFu, s, o);
    if (lane == 0) reds[w] = s;
    __syncthreads();
    s = reds[0];
    #pragma unroll
    for (int i=1;i<8;i++) s += reds[i];
    const float inv = 1.0f / s;
    v0.x*=inv; v0.y*=inv; v0.z*=inv; v0.w*=inv;
    v1.x*=inv; v1.y*=inv; v1.z*=inv; v1.w*=inv;
    row[t] = v0; row[t+256] = v1;
}

// ---------------- ctx = P @ V ----------------
#define VSS 6912

__global__ void __launch_bounds__(256, 2) attn_av_k(
    const float* __restrict__ P, const float* __restrict__ V, float* __restrict__ Ctx)
{
    extern __shared__ float sm[];
    const int tid  = threadIdx.x;
    const int z = blockIdx.y, b = z >> 4, h = z & 15;
    const int bm = blockIdx.x*128;
    const int lane = tid & 31, warp = tid >> 5;
    const int wm = warp >> 1, wn = warp & 1;
    const int gid = lane >> 2, t4 = lane & 3;

    float acc[2][4][4];
    #pragma unroll
    for (int a=0;a<2;a++)
    #pragma unroll
    for (int c=0;c<4;c++)
    #pragma unroll
    for (int i=0;i<4;i++) acc[a][c][i] = 0.f;

    const int ar = tid >> 3, ac4 = tid & 7;
    const int vr = tid >> 4, vc4 = tid & 15;
    const float* Pp = P + (size_t)z*LL_*LL_ + (size_t)(bm+ar)*LL_ + ac4*4;
    const float* Vp = V + ((size_t)(b*LL_ + vr)*HH_ + h)*DH_ + vc4*4;
    const int KT = LL_/32;

    auto issue = [&](int t){
        float* Ps = sm + (t&1)*VSS;
        float* Vs = Ps + 4608;
        const int k0 = t*32;
        #pragma unroll
        for (int i=0;i<4;i++) cp16(Ps + (ar+32*i)*36 + ac4*4, Pp + k0 + (size_t)(32*i)*LL_);
        #pragma unroll
        for (int i=0;i<2;i++) cp16(Vs + (vr+16*i)*72 + vc4*4, Vp + (size_t)(k0+16*i)*1024);
        cp_commit();
    };

    issue(0);
    for (int t = 0; t < KT; t++){
        if (t+1 < KT){ issue(t+1); cp_wait<1>(); }
        else         { cp_wait<0>(); }
        __syncthreads();
        const float* Ps = sm + (t&1)*VSS;
        const float* Vs = Ps + 4608;
        #pragma unroll
        for (int ks=0;ks<4;ks++){
            uint32_t a[2][4], bfr[4][2];
            #pragma unroll
            for (int mi=0;mi<2;mi++){
                const int r0 = (wm*32 + mi*16 + gid)*36 + ks*8 + t4;
                a[mi][0]=f2tf(Ps[r0]);     a[mi][1]=f2tf(Ps[r0+8*36]);
                a[mi][2]=f2tf(Ps[r0+4]);   a[mi][3]=f2tf(Ps[r0+8*36+4]);
            }
            #pragma unroll
            for (int ni=0;ni<4;ni++){
                const int c0 = wn*32 + ni*8 + gid;
                bfr[ni][0] = f2tf(Vs[(ks*8+t4)*72 + c0]);
                bfr[ni][1] = f2tf(Vs[(ks*8+t4+4)*72 + c0]);
            }
            #pragma unroll
            for (int mi=0;mi<2;mi++)
            #pragma unroll
            for (int ni=0;ni<4;ni++)
                mma_tf32(acc[mi][ni], a[mi], bfr[ni]);
        }
        __syncthreads();
    }

    #pragma unroll
    for (int mi=0;mi<2;mi++)
    #pragma unroll
    for (int ni=0;ni<4;ni++){
        const int row0 = bm + wm*32 + mi*16 + gid;
        const int col0 = wn*32 + ni*8 + t4*2;
        #pragma unroll
        for (int i=0;i<4;i++){
            const int row = row0 + ((i>=2)?8:0);
            const int col = col0 + (i&1);
            Ctx[((size_t)(b*LL_ + row)*HH_ + h)*DH_ + col] = acc[mi][ni][i];
        }
    }
}

// ---------------- launch ----------------
extern "C" void kernel_launch(void* const* d_in, const int* in_sizes, int n_in,
                              void* d_out, int out_size)
{
    const float* x     = (const float*)d_in[0];
    const float* ln1_w = (const float*)d_in[1];
    const float* ln1_b = (const float*)d_in[2];
    const float* wq    = (const float*)d_in[3];
    const float* bq    = (const float*)d_in[4];
    const float* wk    = (const float*)d_in[5];
    const float* bk    = (const float*)d_in[6];
    const float* wv    = (const float*)d_in[7];
    const float* bv    = (const float*)d_in[8];
    const float* wo    = (const float*)d_in[9];
    const float* bo    = (const float*)d_in[10];
    const float* ln2_w = (const float*)d_in[11];
    const float* ln2_b = (const float*)d_in[12];
    const float* wu    = (const float*)d_in[13];
    const float* bu    = (const float*)d_in[14];
    const float* wd    = (const float*)d_in[15];
    const float* bd    = (const float*)d_in[16];
    float* out = (float*)d_out;

    float *xn,*q,*k,*v,*ctx,*hidden,*hn,*up,*S;
    cudaGetSymbolAddress((void**)&xn,  g_xn);
    cudaGetSymbolAddress((void**)&q,   g_q);
    cudaGetSymbolAddress((void**)&k,   g_k);
    cudaGetSymbolAddress((void**)&v,   g_v);
    cudaGetSymbolAddress((void**)&ctx, g_ctx);
    cudaGetSymbolAddress((void**)&hidden, g_hidden);
    cudaGetSymbolAddress((void**)&hn,  g_hn);
    cudaGetSymbolAddress((void**)&up,  g_up);
    cudaGetSymbolAddress((void**)&S,   g_S);

    const int SMG = 2*GSS*4;   // 70656
    const int SMV = 2*VSS*4;   // 55296
    cudaFuncSetAttribute(gemm_k<0,1,1>, cudaFuncAttributeMaxDynamicSharedMemorySize, SMG);
    cudaFuncSetAttribute(gemm_k<0,0,2>, cudaFuncAttributeMaxDynamicSharedMemorySize, SMG);
    cudaFuncSetAttribute(gemm_k<1,0,2>, cudaFuncAttributeMaxDynamicSharedMemorySize, SMG);
    cudaFuncSetAttribute(gemm_k<2,0,2>, cudaFuncAttributeMaxDynamicSharedMemorySize, SMG);
    cudaFuncSetAttribute(attn_av_k,     cudaFuncAttributeMaxDynamicSharedMemorySize, SMV);

    const dim3 blk(256);
    const dim3 gE(EE_/128, NTOK/128);    // (8, 32)
    const dim3 gF(FF_/128, NTOK/128);    // (32, 32)

    // 1. LN1
    ln_k<<<NTOK, blk>>>(x, ln1_w, ln1_b, xn);
    // 2. Q, K (A-split 2-MMA), V (single)
    gemm_k<0,1,1><<<gE, blk, SMG>>>(xn, wq, bq, nullptr, q, NTOK, EE_, EE_);
    gemm_k<0,1,1><<<gE, blk, SMG>>>(xn, wk, bk, nullptr, k, NTOK, EE_, EE_);
    gemm_k<0,0,2><<<gE, blk, SMG>>>(xn, wv, bv, nullptr, v, NTOK, EE_, EE_);
    // 3. scores (full split), softmax (shuffle), context
    attn_score_k<<<dim3(LL_/128, LL_/128, NZ), blk>>>(q, k, S);
    softmax_k   <<<dim3(LL_, NZ), blk>>>(S);
    attn_av_k   <<<dim3(LL_/128, NZ), blk, SMV>>>(S, v, ctx);
    // 4. O proj + residual
    gemm_k<1,0,2><<<gE, blk, SMG>>>(ctx, wo, bo, x, hidden, NTOK, EE_, EE_);
    // 5. LN2 + FFN
    ln_k<<<NTOK, blk>>>(hidden, ln2_w, ln2_b, hn);
    gemm_k<2,0,2><<<gF, blk, SMG>>>(hn, wu, bu, nullptr, up, NTOK, FF_, EE_);
    gemm_k<1,0,2><<<gE, blk, SMG>>>(up, wd, bd, hidden, out, NTOK, EE_, FF_);
    (void)in_sizes; (void)n_in; (void)out_size;
}